// round 2
// baseline (speedup 1.0000x reference)
#include <cuda_runtime.h>
#include <math.h>

#define BATCH  2
#define NHEADS 16
#define BH     32       // BATCH*NHEADS
#define SQ     2048     // MAX_LEN (query rows)
#define SK     4096     // key/value rows
#define DH     64
#define QT     64
#define KTILE  64

// ---------------- scratch (static device globals; no allocs) ----------------
__device__ int   g_posq[BATCH * SQ];
__device__ float g_cosT[SK * 16];
__device__ float g_sinT[SK * 16];
__device__ float g_qr[BH * SQ * DH];       // rope'd + scaled Q  (16.8 MB)
__device__ float g_kr[BH * SK * DH];       // rope'd K           (33.5 MB)

// ---------------- kernel 1: gather query positions from skip_mask -----------
// candA/candB: the two 8192-element inputs (pos_full and skip_mask, order and
// dtype unknown). Detect which is skip_mask and its element width on-device.
__global__ void build_idx_kernel(const void* candA, const void* candB) {
    __shared__ int warp_sums[32];
    const int b   = blockIdx.x;
    const int tid = threadIdx.x;          // 1024 threads

    // ---- detect skip_mask pointer ----
    const int*   ai = (const int*)candA;
    const float* af = (const float*)candA;
    const int*   bi = (const int*)candB;
    const float* bf = (const float*)candB;
    bool a_is_pos = (ai[1] == 1 && ai[2] == 2 && ai[3] == 3 && ai[100] == 100) ||
                    (af[1] == 1.0f && af[2] == 2.0f && af[3] == 3.0f && af[100] == 100.0f);
    bool b_is_pos = (bi[1] == 1 && bi[2] == 2 && bi[3] == 3 && bi[100] == 100) ||
                    (bf[1] == 1.0f && bf[2] == 2.0f && bf[3] == 3.0f && bf[100] == 100.0f);
    const void* skipv = a_is_pos ? candB : (b_is_pos ? candA : candB);

    // ---- detect skip element width (1 byte vs 4 bytes) ----
    const unsigned int* sw = (const unsigned int*)skipv;
    bool w4 = true;
#pragma unroll
    for (int i = 0; i < 32; i++) {
        unsigned int x = sw[i];
        w4 = w4 && (x <= 1u || x == 0x3f800000u);   // int32 0/1 or float 1.0
    }
    const unsigned char* s8  = (const unsigned char*)skipv;
    const unsigned int*  s32 = (const unsigned int*)skipv;

    // default-fill
    g_posq[b * SQ + tid * 2]     = 0;
    g_posq[b * SQ + tid * 2 + 1] = 0;
    __syncthreads();

    const int base = tid * 4;
    int flags[4]; int c = 0;
#pragma unroll
    for (int u = 0; u < 4; u++) {
        int idx = b * SK + base + u;
        flags[u] = (w4 ? (s32[idx] != 0u) : (s8[idx] != 0)) ? 1 : 0;
        c += flags[u];
    }
    const int lane = tid & 31, warp = tid >> 5;
    int pre = c;
#pragma unroll
    for (int o = 1; o < 32; o <<= 1) {
        int t = __shfl_up_sync(0xffffffffu, pre, o);
        if (lane >= o) pre += t;
    }
    if (lane == 31) warp_sums[warp] = pre;
    __syncthreads();
    if (warp == 0) {
        int s = warp_sums[lane];
#pragma unroll
        for (int o = 1; o < 32; o <<= 1) {
            int t = __shfl_up_sync(0xffffffffu, s, o);
            if (lane >= o) s += t;
        }
        warp_sums[lane] = s;
    }
    __syncthreads();
    int offset = pre - c + (warp ? warp_sums[warp - 1] : 0);  // exclusive prefix
#pragma unroll
    for (int u = 0; u < 4; u++) {
        if (flags[u] && offset < SQ)
            g_posq[b * SQ + offset] = base + u;   // pos_full[b, j] == j
        offset += flags[u];
    }
}

// ---------------- kernel 2: cos/sin table ------------------------------------
__global__ void build_tab_kernel() {
    int i = blockIdx.x * blockDim.x + threadIdx.x;
    if (i >= SK * 16) return;
    int p = i >> 4, f = i & 15;
    float invf = (float)(1.0 / pow(10000.0, (double)(2 * f) / 32.0));
    float ang  = (float)p * invf;
    g_cosT[i] = cosf(ang);
    g_sinT[i] = sinf(ang);
}

// ---------------- kernel 3: RoPE on Q (scaled by 1/sqrt(D)) ------------------
__global__ void rope_q_kernel(const float* __restrict__ q) {
    int t = blockIdx.x * blockDim.x + threadIdx.x;
    if (t >= BH * SQ * 32) return;
    int u   = t & 31;
    int row = t >> 5;                      // (b*NH+h)*SQ + r
    int b   = row / (NHEADS * SQ);
    int r   = row & (SQ - 1);
    const float* x = q    + (size_t)row * DH;
    float*       y = g_qr + (size_t)row * DH;
    const float sc = 0.125f;
    if (u < 16) {
        int pos = g_posq[b * SQ + r];
        pos = min(max(pos, 0), SK - 1);
        float c  = g_cosT[pos * 16 + u];
        float s2 = g_sinT[pos * 16 + u];
        float x1 = x[u], x2 = x[u + 16];
        y[u]      = (x1 * c - x2 * s2) * sc;
        y[u + 16] = (x2 * c + x1 * s2) * sc;
    } else {
        int d = u + 16;                    // 32..47
        y[d]      = x[d] * sc;
        y[d + 16] = x[d + 16] * sc;
    }
}

// ---------------- kernel 4: RoPE on K (position == row index) ---------------
__global__ void rope_k_kernel(const float* __restrict__ k) {
    int t = blockIdx.x * blockDim.x + threadIdx.x;
    if (t >= BH * SK * 32) return;
    int u   = t & 31;
    int row = t >> 5;                      // (b*NH+h)*SK + r
    int r   = row & (SK - 1);
    const float* x = k    + (size_t)row * DH;
    float*       y = g_kr + (size_t)row * DH;
    if (u < 16) {
        float c  = g_cosT[r * 16 + u];
        float s2 = g_sinT[r * 16 + u];
        float x1 = x[u], x2 = x[u + 16];
        y[u]      = x1 * c - x2 * s2;
        y[u + 16] = x2 * c + x1 * s2;
    } else {
        int d = u + 16;
        y[d]      = x[d];
        y[d + 16] = x[d + 16];
    }
}

// ---------------- kernel 5: flash attention ----------------------------------
// Block: 128 threads. Tile: 64 queries x 64 keys. Thread microtile:
//   QK: queries (ty + 16i), keys (tx + 8j)   -> conflict-free scalar LDS
//   PV: queries (ty + 16i), dims (8*tx + j)  -> float4 V loads, coalesced STG
__global__ __launch_bounds__(128)
void attn_kernel(const float* __restrict__ v, float* __restrict__ out) {
    extern __shared__ float sm[];
    float* qs  = sm;                 // [64][65]
    float* kps = sm + QT * 65;       // [64][65]  K tile, then P tile
    float* vs  = sm + 2 * QT * 65;   // [64][64]

    const int bh  = blockIdx.y;
    const int qt  = (int)gridDim.x - 1 - (int)blockIdx.x;   // heavy-first
    const int b   = bh >> 4;
    const int q0  = qt * QT;
    const int tid = threadIdx.x;
    const int tx  = tid & 7;
    const int ty  = tid >> 3;        // 0..15

    const float* qr = g_qr + ((size_t)bh * SQ + q0) * DH;
    const float* kr = g_kr + (size_t)bh * SK * DH;
    const float* vp = v    + (size_t)bh * SK * DH;

    // load Q tile (row stride 65 in smem)
#pragma unroll
    for (int i = 0; i < 8; i++) {
        int fid = tid + i * 128;
        int r = fid >> 4, c = (fid & 15) * 4;
        float4 f = *(const float4*)(qr + r * DH + c);
        float* dst = qs + r * 65 + c;
        dst[0] = f.x; dst[1] = f.y; dst[2] = f.z; dst[3] = f.w;
    }
    int p[4];
#pragma unroll
    for (int i = 0; i < 4; i++) p[i] = g_posq[b * SQ + q0 + ty + 16 * i];
    const int pmin = g_posq[b * SQ + q0];
    const int pmax = g_posq[b * SQ + q0 + QT - 1];
    const int nkt  = pmax / KTILE + 1;

    float m[4], l[4], o[4][8];
#pragma unroll
    for (int i = 0; i < 4; i++) {
        m[i] = -1e30f; l[i] = 0.f;
#pragma unroll
        for (int j = 0; j < 8; j++) o[i][j] = 0.f;
    }

    for (int t = 0; t < nkt; t++) {
        const int k0 = t * KTILE;
        __syncthreads();   // previous tile's smem reads done
        // load K and V tiles
#pragma unroll
        for (int i = 0; i < 8; i++) {
            int fid = tid + i * 128;
            int r = fid >> 4, c = (fid & 15) * 4;
            float4 f = *(const float4*)(kr + (size_t)(k0 + r) * DH + c);
            float* dst = kps + r * 65 + c;
            dst[0] = f.x; dst[1] = f.y; dst[2] = f.z; dst[3] = f.w;
            float4 g2 = *(const float4*)(vp + (size_t)(k0 + r) * DH + c);
            *(float4*)(vs + r * DH + c) = g2;
        }
        __syncthreads();

        // S = Q * K^T
        float s[4][8];
#pragma unroll
        for (int i = 0; i < 4; i++)
#pragma unroll
            for (int j = 0; j < 8; j++) s[i][j] = 0.f;

#pragma unroll 8
        for (int kk = 0; kk < DH; kk++) {
            float a[4], bb[8];
#pragma unroll
            for (int i = 0; i < 4; i++) a[i] = qs[(ty + 16 * i) * 65 + kk];
#pragma unroll
            for (int j = 0; j < 8; j++) bb[j] = kps[(tx + 8 * j) * 65 + kk];
#pragma unroll
            for (int i = 0; i < 4; i++)
#pragma unroll
                for (int j = 0; j < 8; j++) s[i][j] = fmaf(a[i], bb[j], s[i][j]);
        }

        // causal mask (only boundary tiles need it)
        if (k0 + KTILE - 1 > pmin) {
#pragma unroll
            for (int i = 0; i < 4; i++)
#pragma unroll
                for (int j = 0; j < 8; j++)
                    if (k0 + tx + 8 * j > p[i]) s[i][j] = -1e30f;
        }

        // online softmax (rows reduced over 8 consecutive lanes)
        float fac[4];
#pragma unroll
        for (int i = 0; i < 4; i++) {
            float mt = s[i][0];
#pragma unroll
            for (int j = 1; j < 8; j++) mt = fmaxf(mt, s[i][j]);
            mt = fmaxf(mt, __shfl_xor_sync(0xffffffffu, mt, 1));
            mt = fmaxf(mt, __shfl_xor_sync(0xffffffffu, mt, 2));
            mt = fmaxf(mt, __shfl_xor_sync(0xffffffffu, mt, 4));
            float mn = fmaxf(m[i], mt);
            fac[i] = __expf(m[i] - mn);
            m[i] = mn;
            float rs = 0.f;
#pragma unroll
            for (int j = 0; j < 8; j++) { s[i][j] = __expf(s[i][j] - mn); rs += s[i][j]; }
            rs += __shfl_xor_sync(0xffffffffu, rs, 1);
            rs += __shfl_xor_sync(0xffffffffu, rs, 2);
            rs += __shfl_xor_sync(0xffffffffu, rs, 4);
            l[i] = l[i] * fac[i] + rs;
#pragma unroll
            for (int j = 0; j < 8; j++) o[i][j] *= fac[i];
        }

        __syncthreads();   // all threads done reading K from kps
        // stage P into smem (overwrites K tile)
#pragma unroll
        for (int i = 0; i < 4; i++)
#pragma unroll
            for (int j = 0; j < 8; j++)
                kps[(ty + 16 * i) * 65 + tx + 8 * j] = s[i][j];
        __syncthreads();

        // O += P * V   (thread dims = 8*tx .. 8*tx+7)
#pragma unroll 8
        for (int kk = 0; kk < KTILE; kk++) {
            float a[4];
#pragma unroll
            for (int i = 0; i < 4; i++) a[i] = kps[(ty + 16 * i) * 65 + kk];
            float4 b0 = *(const float4*)(vs + kk * DH + tx * 8);
            float4 b1 = *(const float4*)(vs + kk * DH + tx * 8 + 4);
            float bb[8] = {b0.x, b0.y, b0.z, b0.w, b1.x, b1.y, b1.z, b1.w};
#pragma unroll
            for (int i = 0; i < 4; i++)
#pragma unroll
                for (int j = 0; j < 8; j++) o[i][j] = fmaf(a[i], bb[j], o[i][j]);
        }
    }

    // epilogue: normalize and write (coalesced float4 pairs)
#pragma unroll
    for (int i = 0; i < 4; i++) {
        float inv = 1.0f / l[i];
        float4 w0, w1;
        w0.x = o[i][0] * inv; w0.y = o[i][1] * inv;
        w0.z = o[i][2] * inv; w0.w = o[i][3] * inv;
        w1.x = o[i][4] * inv; w1.y = o[i][5] * inv;
        w1.z = o[i][6] * inv; w1.w = o[i][7] * inv;
        float* orow = out + ((size_t)bh * SQ + q0 + ty + 16 * i) * DH + tx * 8;
        *(float4*)orow       = w0;
        *(float4*)(orow + 4) = w1;
    }
}

// ---------------- launch -----------------------------------------------------
extern "C" void kernel_launch(void* const* d_in, const int* in_sizes, int n_in,
                              void* d_out, int out_size) {
    // Route inputs by element count (robust to ordering):
    //   q = 2*16*2048*64 = 4194304
    //   k,v = 2*16*4096*64 = 8388608 each (k appears before v in both dict
    //        and alphabetical orderings)
    //   pos_full, skip_mask = 8192 each (disambiguated on-device)
    //   mask_full = 33554432 (unused)
    const float* q = nullptr; const float* k = nullptr; const float* v = nullptr;
    const void* cand[2] = {nullptr, nullptr}; int nc = 0;
    for (int i = 0; i < n_in; i++) {
        long long sz = in_sizes[i];
        if (sz == 4194304) { q = (const float*)d_in[i]; }
        else if (sz == 8388608) { if (!k) k = (const float*)d_in[i]; else v = (const float*)d_in[i]; }
        else if (sz == 8192) { if (nc < 2) cand[nc++] = d_in[i]; }
    }
    if (nc == 1) cand[1] = cand[0];
    if (!q || !k || !v || nc == 0) {  // fallback: assume dict order
        q = (const float*)d_in[0]; k = (const float*)d_in[1]; v = (const float*)d_in[2];
        cand[0] = d_in[4]; cand[1] = d_in[5];
    }
    float* out = (float*)d_out;

    build_idx_kernel<<<BATCH, 1024>>>(cand[0], cand[1]);
    build_tab_kernel<<<(SK * 16 + 255) / 256, 256>>>();
    rope_q_kernel<<<(BH * SQ * 32 + 255) / 256, 256>>>(q);
    rope_k_kernel<<<(BH * SK * 32 + 255) / 256, 256>>>(k);

    const int smem_bytes = (QT * 65 * 2 + QT * DH) * (int)sizeof(float);  // 49664
    cudaFuncSetAttribute(attn_kernel,
                         cudaFuncAttributeMaxDynamicSharedMemorySize, smem_bytes);
    dim3 grid(SQ / QT, BH);
    attn_kernel<<<grid, 128, smem_bytes>>>(v, out);
}

// round 3
// speedup vs baseline: 1.1647x; 1.1647x over previous
#include <cuda_runtime.h>
#include <math.h>

#define BATCH  2
#define NHEADS 16
#define BH     32
#define SQ     2048
#define SK     4096
#define DH     64
#define QT     64
#define KTILE  64
#define LS     68          // smem row stride (floats), 16B-aligned, conflict-free

typedef unsigned long long ull;

__device__ __forceinline__ ull pk2(float lo, float hi) {
    ull r; asm("mov.b64 %0,{%1,%2};" : "=l"(r) : "f"(lo), "f"(hi)); return r;
}
__device__ __forceinline__ void upk2(ull v, float& lo, float& hi) {
    asm("mov.b64 {%0,%1},%2;" : "=f"(lo), "=f"(hi) : "l"(v));
}
__device__ __forceinline__ ull ffma2(ull a, ull b, ull c) {
    ull d; asm("fma.rn.f32x2 %0,%1,%2,%3;" : "=l"(d) : "l"(a), "l"(b), "l"(c)); return d;
}
__device__ __forceinline__ ull fmul2(ull a, ull b) {
    ull d; asm("mul.rn.f32x2 %0,%1,%2;" : "=l"(d) : "l"(a), "l"(b)); return d;
}

// ---------------- scratch ----------------
__device__ int   g_posq[BATCH * SQ];
__device__ float g_cosT[SK * 16];
__device__ float g_sinT[SK * 16];
__device__ float g_qr[BH * SQ * DH];
__device__ float g_kr[BH * SK * DH];

// ---------------- kernel 1: gather query positions -------------------------
__global__ void build_idx_kernel(const void* candA, const void* candB) {
    __shared__ int warp_sums[32];
    const int b   = blockIdx.x;
    const int tid = threadIdx.x;          // 1024 threads

    const int*   ai = (const int*)candA;  const float* af = (const float*)candA;
    const int*   bi = (const int*)candB;  const float* bf = (const float*)candB;
    bool a_is_pos = (ai[1] == 1 && ai[2] == 2 && ai[3] == 3 && ai[100] == 100) ||
                    (af[1] == 1.0f && af[2] == 2.0f && af[3] == 3.0f && af[100] == 100.0f);
    bool b_is_pos = (bi[1] == 1 && bi[2] == 2 && bi[3] == 3 && bi[100] == 100) ||
                    (bf[1] == 1.0f && bf[2] == 2.0f && bf[3] == 3.0f && bf[100] == 100.0f);
    const void* skipv = a_is_pos ? candB : (b_is_pos ? candA : candB);

    const unsigned int* sw = (const unsigned int*)skipv;
    bool w4 = true;
#pragma unroll
    for (int i = 0; i < 32; i++) {
        unsigned int x = sw[i];
        w4 = w4 && (x <= 1u || x == 0x3f800000u);
    }
    const unsigned char* s8  = (const unsigned char*)skipv;
    const unsigned int*  s32 = (const unsigned int*)skipv;

    g_posq[b * SQ + tid * 2]     = 0;
    g_posq[b * SQ + tid * 2 + 1] = 0;
    __syncthreads();

    const int base = tid * 4;
    int flags[4]; int c = 0;
#pragma unroll
    for (int u = 0; u < 4; u++) {
        int idx = b * SK + base + u;
        flags[u] = (w4 ? (s32[idx] != 0u) : (s8[idx] != 0)) ? 1 : 0;
        c += flags[u];
    }
    const int lane = tid & 31, warp = tid >> 5;
    int pre = c;
#pragma unroll
    for (int o = 1; o < 32; o <<= 1) {
        int t = __shfl_up_sync(0xffffffffu, pre, o);
        if (lane >= o) pre += t;
    }
    if (lane == 31) warp_sums[warp] = pre;
    __syncthreads();
    if (warp == 0) {
        int s = warp_sums[lane];
#pragma unroll
        for (int o = 1; o < 32; o <<= 1) {
            int t = __shfl_up_sync(0xffffffffu, s, o);
            if (lane >= o) s += t;
        }
        warp_sums[lane] = s;
    }
    __syncthreads();
    int offset = pre - c + (warp ? warp_sums[warp - 1] : 0);
#pragma unroll
    for (int u = 0; u < 4; u++) {
        if (flags[u] && offset < SQ)
            g_posq[b * SQ + offset] = base + u;
        offset += flags[u];
    }
}

// ---------------- kernel 2: cos/sin table ----------------------------------
__global__ void build_tab_kernel() {
    int i = blockIdx.x * blockDim.x + threadIdx.x;
    if (i >= SK * 16) return;
    int p = i >> 4, f = i & 15;
    float invf = (float)(1.0 / pow(10000.0, (double)(2 * f) / 32.0));
    float ang  = (float)p * invf;
    g_cosT[i] = cosf(ang);
    g_sinT[i] = sinf(ang);
}

// ---------------- kernel 3: RoPE on Q (scaled) ------------------------------
__global__ void rope_q_kernel(const float* __restrict__ q) {
    int t = blockIdx.x * blockDim.x + threadIdx.x;
    if (t >= BH * SQ * 32) return;
    int u   = t & 31;
    int row = t >> 5;
    int b   = row / (NHEADS * SQ);
    int r   = row & (SQ - 1);
    const float* x = q    + (size_t)row * DH;
    float*       y = g_qr + (size_t)row * DH;
    const float sc = 0.125f;
    if (u < 16) {
        int pos = g_posq[b * SQ + r];
        pos = min(max(pos, 0), SK - 1);
        float c  = g_cosT[pos * 16 + u];
        float s2 = g_sinT[pos * 16 + u];
        float x1 = x[u], x2 = x[u + 16];
        y[u]      = (x1 * c - x2 * s2) * sc;
        y[u + 16] = (x2 * c + x1 * s2) * sc;
    } else {
        int d = u + 16;
        y[d]      = x[d] * sc;
        y[d + 16] = x[d + 16] * sc;
    }
}

// ---------------- kernel 4: RoPE on K ---------------------------------------
__global__ void rope_k_kernel(const float* __restrict__ k) {
    int t = blockIdx.x * blockDim.x + threadIdx.x;
    if (t >= BH * SK * 32) return;
    int u   = t & 31;
    int row = t >> 5;
    int r   = row & (SK - 1);
    const float* x = k    + (size_t)row * DH;
    float*       y = g_kr + (size_t)row * DH;
    if (u < 16) {
        float c  = g_cosT[r * 16 + u];
        float s2 = g_sinT[r * 16 + u];
        float x1 = x[u], x2 = x[u + 16];
        y[u]      = x1 * c - x2 * s2;
        y[u + 16] = x2 * c + x1 * s2;
    } else {
        int d = u + 16;
        y[d]      = x[d];
        y[d + 16] = x[d + 16];
    }
}

// ---------------- kernel 5: flash attention (f32x2 packed) ------------------
// 128 threads, 64q x 64k tile. QK: packed over reduction (even/odd kk).
// PV: packed over output dims (adjacent d pairs). Microtile 4q x 8k / 4q x 8d.
__global__ __launch_bounds__(128)
void attn_kernel(const float* __restrict__ v, float* __restrict__ out) {
    extern __shared__ float sm[];
    float* qs  = sm;                     // [64][LS]
    float* kps = sm + QT * LS;           // [64][LS]  K tile, then P tile
    float* vs  = sm + 2 * QT * LS;       // [64][LS]

    const int bh  = blockIdx.y;
    const int qt  = (int)gridDim.x - 1 - (int)blockIdx.x;   // heavy-first
    const int b   = bh >> 4;
    const int q0  = qt * QT;
    const int tid = threadIdx.x;
    const int tx  = tid & 7;
    const int ty  = tid >> 3;            // 0..15

    const float* qr = g_qr + ((size_t)bh * SQ + q0) * DH;
    const float* kr = g_kr + (size_t)bh * SK * DH;
    const float* vp = v    + (size_t)bh * SK * DH;

    // load Q tile
#pragma unroll
    for (int i = 0; i < 8; i++) {
        int fid = tid + i * 128;
        int r = fid >> 4, c = (fid & 15) * 4;
        float4 f = *(const float4*)(qr + r * DH + c);
        *(float4*)(qs + r * LS + c) = f;
    }
    int p[4];
#pragma unroll
    for (int i = 0; i < 4; i++) p[i] = g_posq[b * SQ + q0 + ty + 16 * i];
    const int pmin = g_posq[b * SQ + q0];
    const int pmax = g_posq[b * SQ + q0 + QT - 1];
    const int nkt  = pmax / KTILE + 1;

    float m[4], l[4];
    ull o2[4][4];
#pragma unroll
    for (int i = 0; i < 4; i++) {
        m[i] = -1e30f; l[i] = 0.f;
#pragma unroll
        for (int j = 0; j < 4; j++) o2[i][j] = 0ULL;
    }

    const float* qrow[4];
#pragma unroll
    for (int i = 0; i < 4; i++) qrow[i] = qs + (ty + 16 * i) * LS;

    for (int t = 0; t < nkt; t++) {
        const int k0 = t * KTILE;
        __syncthreads();
        // load K and V tiles
#pragma unroll
        for (int i = 0; i < 8; i++) {
            int fid = tid + i * 128;
            int r = fid >> 4, c = (fid & 15) * 4;
            float4 f  = *(const float4*)(kr + (size_t)(k0 + r) * DH + c);
            *(float4*)(kps + r * LS + c) = f;
            float4 g2 = *(const float4*)(vp + (size_t)(k0 + r) * DH + c);
            *(float4*)(vs + r * LS + c) = g2;
        }
        __syncthreads();

        // ---- S = Q K^T : packed over kk (even/odd partial sums) ----
        ull s2[4][8];
#pragma unroll
        for (int i = 0; i < 4; i++)
#pragma unroll
            for (int j = 0; j < 8; j++) s2[i][j] = 0ULL;

#pragma unroll
        for (int kk = 0; kk < DH; kk += 4) {
            ulonglong2 a4[4], b4[8];
#pragma unroll
            for (int i = 0; i < 4; i++)
                a4[i] = *(const ulonglong2*)(qrow[i] + kk);
#pragma unroll
            for (int j = 0; j < 8; j++)
                b4[j] = *(const ulonglong2*)(kps + (tx + 8 * j) * LS + kk);
#pragma unroll
            for (int i = 0; i < 4; i++)
#pragma unroll
                for (int j = 0; j < 8; j++) {
                    s2[i][j] = ffma2(a4[i].x, b4[j].x, s2[i][j]);
                    s2[i][j] = ffma2(a4[i].y, b4[j].y, s2[i][j]);
                }
        }

        // fold even/odd halves
        float s[4][8];
#pragma unroll
        for (int i = 0; i < 4; i++)
#pragma unroll
            for (int j = 0; j < 8; j++) {
                float lo, hi; upk2(s2[i][j], lo, hi);
                s[i][j] = lo + hi;
            }

        // causal mask (boundary tiles only)
        if (k0 + KTILE - 1 > pmin) {
#pragma unroll
            for (int i = 0; i < 4; i++)
#pragma unroll
                for (int j = 0; j < 8; j++)
                    if (k0 + tx + 8 * j > p[i]) s[i][j] = -1e30f;
        }

        // online softmax
        float fac[4];
#pragma unroll
        for (int i = 0; i < 4; i++) {
            float mt = s[i][0];
#pragma unroll
            for (int j = 1; j < 8; j++) mt = fmaxf(mt, s[i][j]);
            mt = fmaxf(mt, __shfl_xor_sync(0xffffffffu, mt, 1));
            mt = fmaxf(mt, __shfl_xor_sync(0xffffffffu, mt, 2));
            mt = fmaxf(mt, __shfl_xor_sync(0xffffffffu, mt, 4));
            float mn = fmaxf(m[i], mt);
            fac[i] = __expf(m[i] - mn);
            m[i] = mn;
            float rs = 0.f;
#pragma unroll
            for (int j = 0; j < 8; j++) { s[i][j] = __expf(s[i][j] - mn); rs += s[i][j]; }
            rs += __shfl_xor_sync(0xffffffffu, rs, 1);
            rs += __shfl_xor_sync(0xffffffffu, rs, 2);
            rs += __shfl_xor_sync(0xffffffffu, rs, 4);
            l[i] = l[i] * fac[i] + rs;
            ull f2 = pk2(fac[i], fac[i]);
#pragma unroll
            for (int j = 0; j < 4; j++) o2[i][j] = fmul2(o2[i][j], f2);
        }

        __syncthreads();     // K reads done; reuse kps for P
#pragma unroll
        for (int i = 0; i < 4; i++)
#pragma unroll
            for (int j = 0; j < 8; j++)
                kps[(ty + 16 * i) * LS + tx + 8 * j] = s[i][j];
        __syncthreads();

        // ---- O += P V : packed over adjacent output dims ----
#pragma unroll
        for (int kk = 0; kk < KTILE; kk += 4) {
            float4 pa4[4];
#pragma unroll
            for (int i = 0; i < 4; i++)
                pa4[i] = *(const float4*)(kps + (ty + 16 * i) * LS + kk);
#pragma unroll
            for (int u = 0; u < 4; u++) {
                const float* vr = vs + (kk + u) * LS + tx * 8;
                ulonglong2 vv = *(const ulonglong2*)(vr);
                ulonglong2 vw = *(const ulonglong2*)(vr + 4);
#pragma unroll
                for (int i = 0; i < 4; i++) {
                    float pv = ((const float*)&pa4[i])[u];
                    ull pr = pk2(pv, pv);
                    o2[i][0] = ffma2(pr, vv.x, o2[i][0]);
                    o2[i][1] = ffma2(pr, vv.y, o2[i][1]);
                    o2[i][2] = ffma2(pr, vw.x, o2[i][2]);
                    o2[i][3] = ffma2(pr, vw.y, o2[i][3]);
                }
            }
        }
    }

    // epilogue: normalize and store (reinterpret packed floats directly)
#pragma unroll
    for (int i = 0; i < 4; i++) {
        float inv = 1.0f / l[i];
        ull iv = pk2(inv, inv);
        ulonglong2 w0, w1;
        w0.x = fmul2(o2[i][0], iv); w0.y = fmul2(o2[i][1], iv);
        w1.x = fmul2(o2[i][2], iv); w1.y = fmul2(o2[i][3], iv);
        float* orow = out + ((size_t)bh * SQ + q0 + ty + 16 * i) * DH + tx * 8;
        *(ulonglong2*)orow       = w0;
        *(ulonglong2*)(orow + 4) = w1;
    }
}

// ---------------- launch ------------------------------------------------------
extern "C" void kernel_launch(void* const* d_in, const int* in_sizes, int n_in,
                              void* d_out, int out_size) {
    const float* q = nullptr; const float* k = nullptr; const float* v = nullptr;
    const void* cand[2] = {nullptr, nullptr}; int nc = 0;
    for (int i = 0; i < n_in; i++) {
        long long sz = in_sizes[i];
        if (sz == 4194304) { q = (const float*)d_in[i]; }
        else if (sz == 8388608) { if (!k) k = (const float*)d_in[i]; else v = (const float*)d_in[i]; }
        else if (sz == 8192) { if (nc < 2) cand[nc++] = d_in[i]; }
    }
    if (nc == 1) cand[1] = cand[0];
    if (!q || !k || !v || nc == 0) {
        q = (const float*)d_in[0]; k = (const float*)d_in[1]; v = (const float*)d_in[2];
        cand[0] = d_in[4]; cand[1] = d_in[5];
    }
    float* out = (float*)d_out;

    build_idx_kernel<<<BATCH, 1024>>>(cand[0], cand[1]);
    build_tab_kernel<<<(SK * 16 + 255) / 256, 256>>>();
    rope_q_kernel<<<(BH * SQ * 32 + 255) / 256, 256>>>(q);
    rope_k_kernel<<<(BH * SK * 32 + 255) / 256, 256>>>(k);

    const int smem_bytes = 3 * QT * LS * (int)sizeof(float);  // 52224
    cudaFuncSetAttribute(attn_kernel,
                         cudaFuncAttributeMaxDynamicSharedMemorySize, smem_bytes);
    dim3 grid(SQ / QT, BH);
    attn_kernel<<<grid, 128, smem_bytes>>>(v, out);
}

// round 4
// speedup vs baseline: 1.1673x; 1.0022x over previous
#include <cuda_runtime.h>
#include <math.h>

#define BATCH  2
#define NHEADS 16
#define BH     32
#define SQ     2048
#define SK     4096
#define DH     64
#define QT     64
#define KTILE  64
#define LS     68          // smem row stride (floats), 16B-aligned, conflict-free

typedef unsigned long long ull;

__device__ __forceinline__ ull pk2(float lo, float hi) {
    ull r; asm("mov.b64 %0,{%1,%2};" : "=l"(r) : "f"(lo), "f"(hi)); return r;
}
__device__ __forceinline__ void upk2(ull v, float& lo, float& hi) {
    asm("mov.b64 {%0,%1},%2;" : "=f"(lo), "=f"(hi) : "l"(v));
}
__device__ __forceinline__ ull ffma2(ull a, ull b, ull c) {
    ull d; asm("fma.rn.f32x2 %0,%1,%2,%3;" : "=l"(d) : "l"(a), "l"(b), "l"(c)); return d;
}
__device__ __forceinline__ ull fmul2(ull a, ull b) {
    ull d; asm("mul.rn.f32x2 %0,%1,%2;" : "=l"(d) : "l"(a), "l"(b)); return d;
}

// ---------------- scratch ----------------
__device__ int   g_posq[BATCH * SQ];
__device__ float g_cosT[SK * 16];
__device__ float g_sinT[SK * 16];
__device__ float g_qr[BH * SQ * DH];
__device__ float g_kr[BH * SK * DH];

// ---------------- kernel 1: gather query positions -------------------------
__global__ void build_idx_kernel(const void* candA, const void* candB) {
    __shared__ int warp_sums[32];
    const int b   = blockIdx.x;
    const int tid = threadIdx.x;          // 1024 threads

    const int*   ai = (const int*)candA;  const float* af = (const float*)candA;
    const int*   bi = (const int*)candB;  const float* bf = (const float*)candB;
    bool a_is_pos = (ai[1] == 1 && ai[2] == 2 && ai[3] == 3 && ai[100] == 100) ||
                    (af[1] == 1.0f && af[2] == 2.0f && af[3] == 3.0f && af[100] == 100.0f);
    bool b_is_pos = (bi[1] == 1 && bi[2] == 2 && bi[3] == 3 && bi[100] == 100) ||
                    (bf[1] == 1.0f && bf[2] == 2.0f && bf[3] == 3.0f && bf[100] == 100.0f);
    const void* skipv = a_is_pos ? candB : (b_is_pos ? candA : candB);

    const unsigned int* sw = (const unsigned int*)skipv;
    bool w4 = true;
#pragma unroll
    for (int i = 0; i < 32; i++) {
        unsigned int x = sw[i];
        w4 = w4 && (x <= 1u || x == 0x3f800000u);
    }
    const unsigned char* s8  = (const unsigned char*)skipv;
    const unsigned int*  s32 = (const unsigned int*)skipv;

    g_posq[b * SQ + tid * 2]     = 0;
    g_posq[b * SQ + tid * 2 + 1] = 0;
    __syncthreads();

    const int base = tid * 4;
    int flags[4]; int c = 0;
#pragma unroll
    for (int u = 0; u < 4; u++) {
        int idx = b * SK + base + u;
        flags[u] = (w4 ? (s32[idx] != 0u) : (s8[idx] != 0)) ? 1 : 0;
        c += flags[u];
    }
    const int lane = tid & 31, warp = tid >> 5;
    int pre = c;
#pragma unroll
    for (int o = 1; o < 32; o <<= 1) {
        int t = __shfl_up_sync(0xffffffffu, pre, o);
        if (lane >= o) pre += t;
    }
    if (lane == 31) warp_sums[warp] = pre;
    __syncthreads();
    if (warp == 0) {
        int s = warp_sums[lane];
#pragma unroll
        for (int o = 1; o < 32; o <<= 1) {
            int t = __shfl_up_sync(0xffffffffu, s, o);
            if (lane >= o) s += t;
        }
        warp_sums[lane] = s;
    }
    __syncthreads();
    int offset = pre - c + (warp ? warp_sums[warp - 1] : 0);
#pragma unroll
    for (int u = 0; u < 4; u++) {
        if (flags[u] && offset < SQ)
            g_posq[b * SQ + offset] = base + u;
        offset += flags[u];
    }
}

// ---------------- kernel 2: cos/sin table ----------------------------------
__global__ void build_tab_kernel() {
    int i = blockIdx.x * blockDim.x + threadIdx.x;
    if (i >= SK * 16) return;
    int p = i >> 4, f = i & 15;
    float invf = (float)(1.0 / pow(10000.0, (double)(2 * f) / 32.0));
    float ang  = (float)p * invf;
    g_cosT[i] = cosf(ang);
    g_sinT[i] = sinf(ang);
}

// ---------------- kernel 3: RoPE on Q (scaled) ------------------------------
__global__ void rope_q_kernel(const float* __restrict__ q) {
    int t = blockIdx.x * blockDim.x + threadIdx.x;
    if (t >= BH * SQ * 32) return;
    int u   = t & 31;
    int row = t >> 5;
    int b   = row / (NHEADS * SQ);
    int r   = row & (SQ - 1);
    const float* x = q    + (size_t)row * DH;
    float*       y = g_qr + (size_t)row * DH;
    const float sc = 0.125f;
    if (u < 16) {
        int pos = g_posq[b * SQ + r];
        pos = min(max(pos, 0), SK - 1);
        float c  = g_cosT[pos * 16 + u];
        float s2 = g_sinT[pos * 16 + u];
        float x1 = x[u], x2 = x[u + 16];
        y[u]      = (x1 * c - x2 * s2) * sc;
        y[u + 16] = (x2 * c + x1 * s2) * sc;
    } else {
        int d = u + 16;
        y[d]      = x[d] * sc;
        y[d + 16] = x[d + 16] * sc;
    }
}

// ---------------- kernel 4: RoPE on K ---------------------------------------
__global__ void rope_k_kernel(const float* __restrict__ k) {
    int t = blockIdx.x * blockDim.x + threadIdx.x;
    if (t >= BH * SK * 32) return;
    int u   = t & 31;
    int row = t >> 5;
    int r   = row & (SK - 1);
    const float* x = k    + (size_t)row * DH;
    float*       y = g_kr + (size_t)row * DH;
    if (u < 16) {
        float c  = g_cosT[r * 16 + u];
        float s2 = g_sinT[r * 16 + u];
        float x1 = x[u], x2 = x[u + 16];
        y[u]      = x1 * c - x2 * s2;
        y[u + 16] = x2 * c + x1 * s2;
    } else {
        int d = u + 16;
        y[d]      = x[d];
        y[d + 16] = x[d + 16];
    }
}

// ---------------- kernel 5: flash attention (f32x2 packed) ------------------
// 128 threads, 64q x 64k tile. QK: packed over reduction (even/odd kk).
// PV: packed over output dims (adjacent d pairs). Microtile 4q x 8k / 4q x 8d.
__global__ __launch_bounds__(128)
void attn_kernel(const float* __restrict__ v, float* __restrict__ out) {
    extern __shared__ float sm[];
    float* qs  = sm;                     // [64][LS]
    float* kps = sm + QT * LS;           // [64][LS]  K tile, then P tile
    float* vs  = sm + 2 * QT * LS;       // [64][LS]

    const int bh  = blockIdx.y;
    const int qt  = (int)gridDim.x - 1 - (int)blockIdx.x;   // heavy-first
    const int b   = bh >> 4;
    const int q0  = qt * QT;
    const int tid = threadIdx.x;
    const int tx  = tid & 7;
    const int ty  = tid >> 3;            // 0..15

    const float* qr = g_qr + ((size_t)bh * SQ + q0) * DH;
    const float* kr = g_kr + (size_t)bh * SK * DH;
    const float* vp = v    + (size_t)bh * SK * DH;

    // load Q tile
#pragma unroll
    for (int i = 0; i < 8; i++) {
        int fid = tid + i * 128;
        int r = fid >> 4, c = (fid & 15) * 4;
        float4 f = *(const float4*)(qr + r * DH + c);
        *(float4*)(qs + r * LS + c) = f;
    }
    int p[4];
#pragma unroll
    for (int i = 0; i < 4; i++) p[i] = g_posq[b * SQ + q0 + ty + 16 * i];
    const int pmin = g_posq[b * SQ + q0];
    const int pmax = g_posq[b * SQ + q0 + QT - 1];
    const int nkt  = pmax / KTILE + 1;

    float m[4], l[4];
    ull o2[4][4];
#pragma unroll
    for (int i = 0; i < 4; i++) {
        m[i] = -1e30f; l[i] = 0.f;
#pragma unroll
        for (int j = 0; j < 4; j++) o2[i][j] = 0ULL;
    }

    const float* qrow[4];
#pragma unroll
    for (int i = 0; i < 4; i++) qrow[i] = qs + (ty + 16 * i) * LS;

    for (int t = 0; t < nkt; t++) {
        const int k0 = t * KTILE;
        __syncthreads();
        // load K and V tiles
#pragma unroll
        for (int i = 0; i < 8; i++) {
            int fid = tid + i * 128;
            int r = fid >> 4, c = (fid & 15) * 4;
            float4 f  = *(const float4*)(kr + (size_t)(k0 + r) * DH + c);
            *(float4*)(kps + r * LS + c) = f;
            float4 g2 = *(const float4*)(vp + (size_t)(k0 + r) * DH + c);
            *(float4*)(vs + r * LS + c) = g2;
        }
        __syncthreads();

        // ---- S = Q K^T : packed over kk (even/odd partial sums) ----
        ull s2[4][8];
#pragma unroll
        for (int i = 0; i < 4; i++)
#pragma unroll
            for (int j = 0; j < 8; j++) s2[i][j] = 0ULL;

#pragma unroll
        for (int kk = 0; kk < DH; kk += 4) {
            ulonglong2 a4[4], b4[8];
#pragma unroll
            for (int i = 0; i < 4; i++)
                a4[i] = *(const ulonglong2*)(qrow[i] + kk);
#pragma unroll
            for (int j = 0; j < 8; j++)
                b4[j] = *(const ulonglong2*)(kps + (tx + 8 * j) * LS + kk);
#pragma unroll
            for (int i = 0; i < 4; i++)
#pragma unroll
                for (int j = 0; j < 8; j++) {
                    s2[i][j] = ffma2(a4[i].x, b4[j].x, s2[i][j]);
                    s2[i][j] = ffma2(a4[i].y, b4[j].y, s2[i][j]);
                }
        }

        // fold even/odd halves
        float s[4][8];
#pragma unroll
        for (int i = 0; i < 4; i++)
#pragma unroll
            for (int j = 0; j < 8; j++) {
                float lo, hi; upk2(s2[i][j], lo, hi);
                s[i][j] = lo + hi;
            }

        // causal mask (boundary tiles only)
        if (k0 + KTILE - 1 > pmin) {
#pragma unroll
            for (int i = 0; i < 4; i++)
#pragma unroll
                for (int j = 0; j < 8; j++)
                    if (k0 + tx + 8 * j > p[i]) s[i][j] = -1e30f;
        }

        // online softmax
        float fac[4];
#pragma unroll
        for (int i = 0; i < 4; i++) {
            float mt = s[i][0];
#pragma unroll
            for (int j = 1; j < 8; j++) mt = fmaxf(mt, s[i][j]);
            mt = fmaxf(mt, __shfl_xor_sync(0xffffffffu, mt, 1));
            mt = fmaxf(mt, __shfl_xor_sync(0xffffffffu, mt, 2));
            mt = fmaxf(mt, __shfl_xor_sync(0xffffffffu, mt, 4));
            float mn = fmaxf(m[i], mt);
            fac[i] = __expf(m[i] - mn);
            m[i] = mn;
            float rs = 0.f;
#pragma unroll
            for (int j = 0; j < 8; j++) { s[i][j] = __expf(s[i][j] - mn); rs += s[i][j]; }
            rs += __shfl_xor_sync(0xffffffffu, rs, 1);
            rs += __shfl_xor_sync(0xffffffffu, rs, 2);
            rs += __shfl_xor_sync(0xffffffffu, rs, 4);
            l[i] = l[i] * fac[i] + rs;
            ull f2 = pk2(fac[i], fac[i]);
#pragma unroll
            for (int j = 0; j < 4; j++) o2[i][j] = fmul2(o2[i][j], f2);
        }

        __syncthreads();     // K reads done; reuse kps for P
#pragma unroll
        for (int i = 0; i < 4; i++)
#pragma unroll
            for (int j = 0; j < 8; j++)
                kps[(ty + 16 * i) * LS + tx + 8 * j] = s[i][j];
        __syncthreads();

        // ---- O += P V : packed over adjacent output dims ----
#pragma unroll
        for (int kk = 0; kk < KTILE; kk += 4) {
            float4 pa4[4];
#pragma unroll
            for (int i = 0; i < 4; i++)
                pa4[i] = *(const float4*)(kps + (ty + 16 * i) * LS + kk);
#pragma unroll
            for (int u = 0; u < 4; u++) {
                const float* vr = vs + (kk + u) * LS + tx * 8;
                ulonglong2 vv = *(const ulonglong2*)(vr);
                ulonglong2 vw = *(const ulonglong2*)(vr + 4);
#pragma unroll
                for (int i = 0; i < 4; i++) {
                    float pv = ((const float*)&pa4[i])[u];
                    ull pr = pk2(pv, pv);
                    o2[i][0] = ffma2(pr, vv.x, o2[i][0]);
                    o2[i][1] = ffma2(pr, vv.y, o2[i][1]);
                    o2[i][2] = ffma2(pr, vw.x, o2[i][2]);
                    o2[i][3] = ffma2(pr, vw.y, o2[i][3]);
                }
            }
        }
    }

    // epilogue: normalize and store (reinterpret packed floats directly)
#pragma unroll
    for (int i = 0; i < 4; i++) {
        float inv = 1.0f / l[i];
        ull iv = pk2(inv, inv);
        ulonglong2 w0, w1;
        w0.x = fmul2(o2[i][0], iv); w0.y = fmul2(o2[i][1], iv);
        w1.x = fmul2(o2[i][2], iv); w1.y = fmul2(o2[i][3], iv);
        float* orow = out + ((size_t)bh * SQ + q0 + ty + 16 * i) * DH + tx * 8;
        *(ulonglong2*)orow       = w0;
        *(ulonglong2*)(orow + 4) = w1;
    }
}

// ---------------- launch ------------------------------------------------------
extern "C" void kernel_launch(void* const* d_in, const int* in_sizes, int n_in,
                              void* d_out, int out_size) {
    const float* q = nullptr; const float* k = nullptr; const float* v = nullptr;
    const void* cand[2] = {nullptr, nullptr}; int nc = 0;
    for (int i = 0; i < n_in; i++) {
        long long sz = in_sizes[i];
        if (sz == 4194304) { q = (const float*)d_in[i]; }
        else if (sz == 8388608) { if (!k) k = (const float*)d_in[i]; else v = (const float*)d_in[i]; }
        else if (sz == 8192) { if (nc < 2) cand[nc++] = d_in[i]; }
    }
    if (nc == 1) cand[1] = cand[0];
    if (!q || !k || !v || nc == 0) {
        q = (const float*)d_in[0]; k = (const float*)d_in[1]; v = (const float*)d_in[2];
        cand[0] = d_in[4]; cand[1] = d_in[5];
    }
    float* out = (float*)d_out;

    build_idx_kernel<<<BATCH, 1024>>>(cand[0], cand[1]);
    build_tab_kernel<<<(SK * 16 + 255) / 256, 256>>>();
    rope_q_kernel<<<(BH * SQ * 32 + 255) / 256, 256>>>(q);
    rope_k_kernel<<<(BH * SK * 32 + 255) / 256, 256>>>(k);

    const int smem_bytes = 3 * QT * LS * (int)sizeof(float);  // 52224
    cudaFuncSetAttribute(attn_kernel,
                         cudaFuncAttributeMaxDynamicSharedMemorySize, smem_bytes);
    dim3 grid(SQ / QT, BH);
    attn_kernel<<<grid, 128, smem_bytes>>>(v, out);
}